// round 16
// baseline (speedup 1.0000x reference)
#include <cuda_runtime.h>

#define FULL 0xffffffffu

static constexpr int B = 256, D = 128, K = 8192;
static constexpr int ENT  = B * (K + 1);            // 2,097,408
static constexpr int NROWS = 500000;
static constexpr long long BANK  = (long long)NROWS * D;   // 64,000,000 floats
static constexpr long long BANK4 = BANK / 4;        // 16,000,000 float4
static constexpr int CBLK = 2048;                   // copy-role blocks
static constexpr int GBLK = 4096;                   // gather-role blocks
static constexpr int TBLK = CBLK + GBLK;            // 6144, period 3: g,g,c
static constexpr int MPB  = 7813;                   // float4 per copy block (ceil)
static constexpr int EPB  = 512;                    // entries per gather block
static constexpr int SCAN_BLK = 489;                // 489*1024 >= NROWS

__device__ int      g_rcnt[NROWS];
__device__ int      g_roff[NROWS];    // exclusive scan within block; becomes cursor
__device__ int      g_bsum[SCAN_BLK];
__device__ int      g_boff[SCAN_BLK];
__device__ unsigned g_ent[ENT];       // row | b<<19 | pos<<27, FULLY row-sorted
__device__ float    g_sc0[ENT];       // view0 exp-scores, sign-flagged
__device__ float    g_sc1[ENT];       // view1 exp-scores, sign-flagged
__device__ uint2    g_fsb[B * 32];    // f_s bf16
__device__ uint2    g_ftb[B * 32];    // f_t bf16
__device__ double   g_sum[2];
__device__ double   g_loss;
__device__ int      g_winner[B];

__device__ __forceinline__ float kINV_T() { return (float)(1.0 / 0.07); }
__device__ __forceinline__ float kMPN()   { return (float)(8192.0 / 500000.0); }
__device__ __forceinline__ float kDENOM() { return (float)(8192.0 / 500000.0 + 1e-7); }

__device__ __forceinline__ uint2 pack4(float4 v) {
    uint2 r;
    asm("cvt.rn.bf16x2.f32 %0, %1, %2;" : "=r"(r.x) : "f"(v.y), "f"(v.x));
    asm("cvt.rn.bf16x2.f32 %0, %1, %2;" : "=r"(r.y) : "f"(v.w), "f"(v.z));
    return r;
}

__device__ __forceinline__ float dotrf(float4 w, uint2 f) {
    float fx = __uint_as_float(f.x << 16);
    float fy = __uint_as_float(f.x & 0xffff0000u);
    float fz = __uint_as_float(f.y << 16);
    float fw = __uint_as_float(f.y & 0xffff0000u);
    return w.x * fx + w.y * fy + w.z * fz + w.w * fw;
}

// --- init: zero row counters, sums, winners, copy-edge scalars, f -> bf16
__global__ void __launch_bounds__(256) k_zero(
        const int* __restrict__ idx,
        const float* __restrict__ f_s, const float* __restrict__ f_t,
        const float* __restrict__ mv1, const float* __restrict__ mv2,
        float* __restrict__ out) {
    int t = blockIdx.x * 256 + threadIdx.x;   // 131072 threads
    #pragma unroll
    for (int u = 0; u < 4; u++) {
        int i = t * 4 + u;
        if (i < NROWS) g_rcnt[i] = 0;
    }
    if (t < 2) g_sum[t] = 0.0;
    if (t == 2) g_loss = 0.0;
    if (t == 3) {
        out[1] = mv1[0]; out[2] = mv1[1]; out[3] = mv1[2];
        out[BANK] = mv1[BANK - 1];
        out[1 + BANK] = mv2[0]; out[2 + BANK] = mv2[1]; out[3 + BANK] = mv2[2];
        out[2 * BANK] = mv2[BANK - 1];
    }
    if (t < B) {
        int my = idx[t];
        int win = 1;
        for (int b2 = t + 1; b2 < B; b2++)
            if (idx[b2] == my) win = 0;
        g_winner[t] = win;
    }
    if (t < 4096) {
        const float4* fs4 = (const float4*)f_s;
        const float4* ft4 = (const float4*)f_t;
        #pragma unroll
        for (int u = 0; u < 2; u++) {
            int i = t * 2 + u;                // < 8192
            g_fsb[i] = pack4(fs4[i]);
            g_ftb[i] = pack4(ft4[i]);
        }
    }
}

// --- histogram per ROW (spread-address atomics ~= LSU floor)
__global__ void __launch_bounds__(256) k_hist(const int* __restrict__ idx,
                                              const int* __restrict__ cidx) {
    int t = blockIdx.x * 256 + threadIdx.x;   // 131072 threads, 4 int4 each
    const int4* c4 = (const int4*)cidx;
    #pragma unroll
    for (int it = 0; it < 4; it++) {
        int4 v = c4[t + it * 131072];
        atomicAdd(&g_rcnt[v.x], 1);
        atomicAdd(&g_rcnt[v.y], 1);
        atomicAdd(&g_rcnt[v.z], 1);
        atomicAdd(&g_rcnt[v.w], 1);
    }
    if (t < B) atomicAdd(&g_rcnt[idx[t]], 1);
}

// --- scan stage A: per-1024 block exclusive scan -> g_roff, block totals -> g_bsum
__global__ void __launch_bounds__(1024) k_scanA() {
    int tid = threadIdx.x;
    int i = blockIdx.x * 1024 + tid;
    int c = (i < NROWS) ? g_rcnt[i] : 0;
    int lane = tid & 31, w = tid >> 5;
    int x = c;
    #pragma unroll
    for (int off = 1; off < 32; off <<= 1) {
        int y = __shfl_up_sync(FULL, x, off);
        if (lane >= off) x += y;
    }
    __shared__ int ws[32];
    if (lane == 31) ws[w] = x;
    __syncthreads();
    if (tid < 32) {                            // full warp participates
        int v = ws[tid];
        int p = v;
        #pragma unroll
        for (int off = 1; off < 32; off <<= 1) {
            int y = __shfl_up_sync(FULL, p, off);
            if (tid >= off) p += y;
        }
        ws[tid] = p - v;                      // exclusive warp base
    }
    __syncthreads();
    int excl = x - c + ws[w];
    if (i < NROWS) g_roff[i] = excl;
    if (tid == 1023) g_bsum[blockIdx.x] = ws[31] + x;
}

// --- scan stage B: exclusive scan of 489 block totals (1 block, full warps)
__global__ void __launch_bounds__(512) k_scanB() {
    int tid = threadIdx.x;
    int c = (tid < SCAN_BLK) ? g_bsum[tid] : 0;
    int lane = tid & 31, w = tid >> 5;
    int x = c;
    #pragma unroll
    for (int off = 1; off < 32; off <<= 1) {
        int y = __shfl_up_sync(FULL, x, off);
        if (lane >= off) x += y;
    }
    __shared__ int ws[16];
    if (lane == 31) ws[w] = x;
    __syncthreads();
    if (tid < 32) {                            // full warp participates
        int v = (tid < 16) ? ws[tid] : 0;
        int p = v;
        #pragma unroll
        for (int off = 1; off < 32; off <<= 1) {
            int y = __shfl_up_sync(FULL, p, off);
            if (tid >= off) p += y;
        }
        if (tid < 16) ws[tid] = p - v;
    }
    __syncthreads();
    if (tid < SCAN_BLK) g_boff[tid] = x - c + ws[w];
}

// --- scatter entries into row-sorted order (base added at use)
__global__ void __launch_bounds__(256) k_scatter(const int* __restrict__ idx,
                                                 const int* __restrict__ cidx) {
    int t = blockIdx.x * 256 + threadIdx.x;   // 131072 threads
    const int4* c4 = (const int4*)cidx;
    #pragma unroll
    for (int it = 0; it < 4; it++) {
        int q = t + it * 131072;              // int4 index; 2048 int4 per b
        int4 v = c4[q];
        unsigned b = (unsigned)(q >> 11);
        int rows[4] = {v.x, v.y, v.z, v.w};
        #pragma unroll
        for (int u = 0; u < 4; u++) {
            int row = rows[u];
            int pos = atomicAdd(&g_roff[row], 1) + g_boff[row >> 10];
            g_ent[pos] = (unsigned)row | (b << 19);
        }
    }
    if (t < B) {
        int row = idx[t];
        int pos = atomicAdd(&g_roff[row], 1) + g_boff[row >> 10];
        g_ent[pos] = (unsigned)row | ((unsigned)t << 19) | (1u << 27);
    }
}

// --- fused: copy role (contiguous m range) || gather role (contiguous slabs)
//     bid-interleave keeps roles on ~the same row range -> L2 sharing;
//     row-sorted slabs -> L1 hits on repeated rows
__global__ void __launch_bounds__(256) k_fused(
        const float* __restrict__ mv1, const float* __restrict__ mv2,
        float* __restrict__ out) {
    int bid = blockIdx.x;
    int q = bid / 3;
    int r = bid - q * 3;
    int tid = threadIdx.x;
    int lane = tid & 31;
    int wrp  = tid >> 5;

    if (r == 2) {
        // ===== copy role: contiguous range of float4 positions, both banks
        const float4* b14 = (const float4*)mv1;
        const float4* b24 = (const float4*)mv2;
        float4* out4 = (float4*)out;
        long long mb = (long long)q * MPB;
        for (int mi = tid; mi < MPB; mi += 256) {
            long long m = mb + mi;
            if (m >= BANK4) break;
            float4 c1 = b14[m];
            float4 c2 = b24[m];
            float p1 = __shfl_up_sync(FULL, c1.w, 1);
            float p2 = __shfl_up_sync(FULL, c2.w, 1);
            if (lane == 0 && m > 0) {
                p1 = __ldg(&mv1[4 * m - 1]);
                p2 = __ldg(&mv2[4 * m - 1]);
            }
            if (m != 0) {
                __stcs(&out4[m],         make_float4(p1, c1.x, c1.y, c1.z));
                __stcs(&out4[BANK4 + m], make_float4(p2, c2.x, c2.y, c2.z));
            }
        }
        return;
    }

    // ===== gather role: contiguous slab of row-sorted entries, both views
    int g = q * 2 + r;                        // 0..GBLK-1
    int begin = g * EPB;
    int end = (g == GBLK - 1) ? ENT : begin + EPB;
    const float4* b14 = (const float4*)mv1;
    const float4* b24 = (const float4*)mv2;

    double acc0 = 0.0, acc1 = 0.0;

    for (int e0 = begin + wrp * 8; e0 < end; e0 += 64) {
        int cnt = min(8, end - e0);
        unsigned ent = 0;
        if (lane < cnt) ent = g_ent[e0 + lane];

        float4 w[8];
        float d0[8], d1[8];
        // batch 1: mv1 rows -> view1 (<mv1_row, f_t>)
        #pragma unroll
        for (int j = 0; j < 8; j++) {
            unsigned ej = __shfl_sync(FULL, ent, j);
            w[j] = b14[(long long)(ej & 0x7FFFFu) * 32 + lane];
        }
        #pragma unroll
        for (int j = 0; j < 8; j++) {
            unsigned ej = __shfl_sync(FULL, ent, j);
            uint2 ft = g_ftb[((ej >> 19) & 0xFFu) * 32 + lane];
            d1[j] = dotrf(w[j], ft);
        }
        // batch 2: mv2 rows -> view0 (<mv2_row, f_s>)
        #pragma unroll
        for (int j = 0; j < 8; j++) {
            unsigned ej = __shfl_sync(FULL, ent, j);
            w[j] = b24[(long long)(ej & 0x7FFFFu) * 32 + lane];
        }
        #pragma unroll
        for (int j = 0; j < 8; j++) {
            unsigned ej = __shfl_sync(FULL, ent, j);
            uint2 fs = g_fsb[((ej >> 19) & 0xFFu) * 32 + lane];
            d0[j] = dotrf(w[j], fs);
        }

        #pragma unroll
        for (int off = 16; off > 0; off >>= 1) {
            #pragma unroll
            for (int j = 0; j < 8; j++) {
                d0[j] += __shfl_xor_sync(FULL, d0[j], off);
                d1[j] += __shfl_xor_sync(FULL, d1[j], off);
            }
        }
        float my0 = d0[0], my1 = d1[0];
        #pragma unroll
        for (int j = 1; j < 8; j++)
            if (lane == j) { my0 = d0[j]; my1 = d1[j]; }

        if (lane < cnt) {
            float e0v = expf(my0 * kINV_T());
            float e1v = expf(my1 * kINV_T());
            bool pos = (ent >> 27) != 0;
            g_sc0[e0 + lane] = pos ? -e0v : e0v;
            g_sc1[e0 + lane] = pos ? -e1v : e1v;
            acc0 += (double)e0v;
            acc1 += (double)e1v;
        }
    }

    #pragma unroll
    for (int off = 16; off > 0; off >>= 1) {
        acc0 += __shfl_xor_sync(FULL, acc0, off);
        acc1 += __shfl_xor_sync(FULL, acc1, off);
    }
    __shared__ double shs[16];
    if (lane == 0) { shs[wrp] = acc0; shs[8 + wrp] = acc1; }
    __syncthreads();
    if (tid == 0) {
        double s0 = 0.0, s1 = 0.0;
        #pragma unroll
        for (int j = 0; j < 8; j++) { s0 += shs[j]; s1 += shs[8 + j]; }
        atomicAdd(&g_sum[0], s0);
        atomicAdd(&g_sum[1], s1);
    }
}

// --- loss reduction (blocks 0-511) + momentum scatter update (blocks 512-1023)
//     The update role depends only on g_winner/idx/banks/out, all final before
//     this kernel launches; it rides free on SM slots unused by the loss wave.
__global__ void __launch_bounds__(256) k2_loss(
        const float* __restrict__ f_s, const float* __restrict__ f_t,
        const float* __restrict__ mv1, const float* __restrict__ mv2,
        const int* __restrict__ idx, float* __restrict__ out) {
    if (blockIdx.x >= 512) {
        // ===== update role: one (view, b) unit per block, threads 0-127 active
        int u = blockIdx.x - 512;             // 0..511
        int v = u >> 8;
        int b = u & 255;
        __shared__ float sh[4];
        int t = threadIdx.x;
        bool act = (t < 128) && g_winner[b];
        int row = act ? idx[b] : 0;
        float nv = 0.f;
        if (act) {
            const float* mem = v ? mv2 : mv1;
            const float* f   = v ? f_t : f_s;
            nv = mem[(long long)row * D + t] * 0.5f + f[b * D + t] * 0.5f;
        }
        float s = nv * nv;
        #pragma unroll
        for (int off = 16; off > 0; off >>= 1)
            s += __shfl_xor_sync(FULL, s, off);
        if (t < 128 && (t & 31) == 0) sh[t >> 5] = s;
        __syncthreads();
        if (act) {
            float tot = sh[0] + sh[1] + sh[2] + sh[3];
            float* dst = out + 1 + (size_t)v * BANK + (size_t)row * D;
            dst[t] = nv / sqrtf(tot);
        }
        return;
    }

    double Z0 = g_sum[0] * (500000.0 / (double)ENT);
    double Z1 = g_sum[1] * (500000.0 / (double)ENT);
    float Zf0 = (float)Z0, Zf1 = (float)Z1;

    const int NT = 512 * 256;
    int tid = blockIdx.x * 256 + threadIdx.x;
    double acc = 0.0;

    #pragma unroll 4
    for (int i = tid; i < 2 * ENT; i += NT) {
        int v1 = (i >= ENT);
        float s = v1 ? g_sc1[i - ENT] : g_sc0[i];
        float Zf = v1 ? Zf1 : Zf0;
        float y = fabsf(s) / Zf;
        float t = (s < 0.0f) ? logf(y / (y + kDENOM()))
                             : logf(kMPN() / (y + kDENOM()));
        acc += (double)t;
    }

    #pragma unroll
    for (int off = 16; off > 0; off >>= 1)
        acc += __shfl_xor_sync(FULL, acc, off);
    __shared__ double sh[8];
    int lane = threadIdx.x & 31, wid = threadIdx.x >> 5;
    if (lane == 0) sh[wid] = acc;
    __syncthreads();
    if (threadIdx.x == 0) {
        double s = 0.0;
        for (int j = 0; j < 8; j++) s += sh[j];
        atomicAdd(&g_loss, s);
    }
}

__global__ void k_final(float* __restrict__ out) {
    out[0] = (float)(-g_loss / 256.0);
}

extern "C" void kernel_launch(void* const* d_in, const int* in_sizes, int n_in,
                              void* d_out, int out_size) {
    const float* f_s  = (const float*)d_in[0];
    const float* f_t  = (const float*)d_in[1];
    const float* mv1  = (const float*)d_in[2];
    const float* mv2  = (const float*)d_in[3];
    const int*   idx  = (const int*)d_in[4];
    const int*   cidx = (const int*)d_in[5];
    float* out = (float*)d_out;

    k_zero<<<512, 256>>>(idx, f_s, f_t, mv1, mv2, out);
    k_hist<<<512, 256>>>(idx, cidx);
    k_scanA<<<SCAN_BLK, 1024>>>();
    k_scanB<<<1, 512>>>();
    k_scatter<<<512, 256>>>(idx, cidx);
    k_fused<<<TBLK, 256>>>(mv1, mv2, out);
    k2_loss<<<1024, 256>>>(f_s, f_t, mv1, mv2, idx, out);
    k_final<<<1, 1>>>(out);
}

// round 17
// speedup vs baseline: 1.0210x; 1.0210x over previous
#include <cuda_runtime.h>

#define FULL 0xffffffffu

static constexpr int B = 256, D = 128, K = 8192;
static constexpr int ENT  = B * (K + 1);            // 2,097,408
static constexpr int NROWS = 500000;
static constexpr long long BANK  = (long long)NROWS * D;   // 64,000,000 floats
static constexpr long long BANK4 = BANK / 4;        // 16,000,000 float4
static constexpr int CBLK = 2048;                   // copy-role blocks
static constexpr int GBLK = 4096;                   // gather-role blocks
static constexpr int TBLK = CBLK + GBLK;            // 6144, period 3: g,g,c
static constexpr int MPB  = 7813;                   // float4 per copy block (ceil)
static constexpr int EPB  = 512;                    // entries per gather block
static constexpr int SCAN_BLK = 489;                // 489*1024 >= NROWS

__device__ int      g_roff[NROWS];    // exclusive scan within block; becomes cursor
__device__ int      g_rcnt[NROWS];
__device__ int      g_bsum[SCAN_BLK];
__device__ int      g_boff[SCAN_BLK];
__device__ unsigned g_ent[ENT];       // row | b<<19 | pos<<27, FULLY row-sorted
__device__ float    g_sc0[ENT];       // view0 exp-scores, sign-flagged
__device__ float    g_sc1[ENT];       // view1 exp-scores, sign-flagged
__device__ uint2    g_fsb[B * 32];    // f_s bf16
__device__ uint2    g_ftb[B * 32];    // f_t bf16
__device__ double   g_sum[2];
__device__ double   g_loss;
__device__ int      g_winner[B];

__device__ __forceinline__ float kINV_T() { return (float)(1.0 / 0.07); }
__device__ __forceinline__ float kMPN()   { return (float)(8192.0 / 500000.0); }
__device__ __forceinline__ float kDENOM() { return (float)(8192.0 / 500000.0 + 1e-7); }

__device__ __forceinline__ uint2 pack4(float4 v) {
    uint2 r;
    asm("cvt.rn.bf16x2.f32 %0, %1, %2;" : "=r"(r.x) : "f"(v.y), "f"(v.x));
    asm("cvt.rn.bf16x2.f32 %0, %1, %2;" : "=r"(r.y) : "f"(v.w), "f"(v.z));
    return r;
}

__device__ __forceinline__ float dotrf(float4 w, uint2 f) {
    float fx = __uint_as_float(f.x << 16);
    float fy = __uint_as_float(f.x & 0xffff0000u);
    float fz = __uint_as_float(f.y << 16);
    float fw = __uint_as_float(f.y & 0xffff0000u);
    return w.x * fx + w.y * fy + w.z * fz + w.w * fw;
}

// --- init: zero row counters, sums, winners, copy-edge scalars, f -> bf16
__global__ void __launch_bounds__(256) k_zero(
        const int* __restrict__ idx,
        const float* __restrict__ f_s, const float* __restrict__ f_t,
        const float* __restrict__ mv1, const float* __restrict__ mv2,
        float* __restrict__ out) {
    int t = blockIdx.x * 256 + threadIdx.x;   // 131072 threads
    #pragma unroll
    for (int u = 0; u < 4; u++) {
        int i = t * 4 + u;
        if (i < NROWS) g_rcnt[i] = 0;
    }
    if (t < 2) g_sum[t] = 0.0;
    if (t == 2) g_loss = 0.0;
    if (t == 3) {
        out[1] = mv1[0]; out[2] = mv1[1]; out[3] = mv1[2];
        out[BANK] = mv1[BANK - 1];
        out[1 + BANK] = mv2[0]; out[2 + BANK] = mv2[1]; out[3 + BANK] = mv2[2];
        out[2 * BANK] = mv2[BANK - 1];
    }
    if (t < B) {
        int my = idx[t];
        int win = 1;
        for (int b2 = t + 1; b2 < B; b2++)
            if (idx[b2] == my) win = 0;
        g_winner[t] = win;
    }
    if (t < 4096) {
        const float4* fs4 = (const float4*)f_s;
        const float4* ft4 = (const float4*)f_t;
        #pragma unroll
        for (int u = 0; u < 2; u++) {
            int i = t * 2 + u;                // < 8192
            g_fsb[i] = pack4(fs4[i]);
            g_ftb[i] = pack4(ft4[i]);
        }
    }
}

// --- histogram per ROW (spread-address atomics ~= LSU floor)
__global__ void __launch_bounds__(256) k_hist(const int* __restrict__ idx,
                                              const int* __restrict__ cidx) {
    int t = blockIdx.x * 256 + threadIdx.x;   // 131072 threads, 4 int4 each
    const int4* c4 = (const int4*)cidx;
    #pragma unroll
    for (int it = 0; it < 4; it++) {
        int4 v = c4[t + it * 131072];
        atomicAdd(&g_rcnt[v.x], 1);
        atomicAdd(&g_rcnt[v.y], 1);
        atomicAdd(&g_rcnt[v.z], 1);
        atomicAdd(&g_rcnt[v.w], 1);
    }
    if (t < B) atomicAdd(&g_rcnt[idx[t]], 1);
}

// --- scan stage A: per-1024 block exclusive scan -> g_roff, block totals -> g_bsum
__global__ void __launch_bounds__(1024) k_scanA() {
    int tid = threadIdx.x;
    int i = blockIdx.x * 1024 + tid;
    int c = (i < NROWS) ? g_rcnt[i] : 0;
    int lane = tid & 31, w = tid >> 5;
    int x = c;
    #pragma unroll
    for (int off = 1; off < 32; off <<= 1) {
        int y = __shfl_up_sync(FULL, x, off);
        if (lane >= off) x += y;
    }
    __shared__ int ws[32];
    if (lane == 31) ws[w] = x;
    __syncthreads();
    if (tid < 32) {                            // full warp participates
        int v = ws[tid];
        int p = v;
        #pragma unroll
        for (int off = 1; off < 32; off <<= 1) {
            int y = __shfl_up_sync(FULL, p, off);
            if (tid >= off) p += y;
        }
        ws[tid] = p - v;                      // exclusive warp base
    }
    __syncthreads();
    int excl = x - c + ws[w];
    if (i < NROWS) g_roff[i] = excl;
    if (tid == 1023) g_bsum[blockIdx.x] = ws[31] + x;
}

// --- scan stage B: exclusive scan of 489 block totals (1 block, full warps)
__global__ void __launch_bounds__(512) k_scanB() {
    int tid = threadIdx.x;
    int c = (tid < SCAN_BLK) ? g_bsum[tid] : 0;
    int lane = tid & 31, w = tid >> 5;
    int x = c;
    #pragma unroll
    for (int off = 1; off < 32; off <<= 1) {
        int y = __shfl_up_sync(FULL, x, off);
        if (lane >= off) x += y;
    }
    __shared__ int ws[16];
    if (lane == 31) ws[w] = x;
    __syncthreads();
    if (tid < 32) {                            // full warp participates
        int v = (tid < 16) ? ws[tid] : 0;
        int p = v;
        #pragma unroll
        for (int off = 1; off < 32; off <<= 1) {
            int y = __shfl_up_sync(FULL, p, off);
            if (tid >= off) p += y;
        }
        if (tid < 16) ws[tid] = p - v;
    }
    __syncthreads();
    if (tid < SCAN_BLK) g_boff[tid] = x - c + ws[w];
}

// --- scatter entries into row-sorted order (base added at use: no scanC kernel)
__global__ void __launch_bounds__(256) k_scatter(const int* __restrict__ idx,
                                                 const int* __restrict__ cidx) {
    int t = blockIdx.x * 256 + threadIdx.x;   // 131072 threads
    const int4* c4 = (const int4*)cidx;
    #pragma unroll
    for (int it = 0; it < 4; it++) {
        int q = t + it * 131072;              // int4 index; 2048 int4 per b
        int4 v = c4[q];
        unsigned b = (unsigned)(q >> 11);
        int rows[4] = {v.x, v.y, v.z, v.w};
        #pragma unroll
        for (int u = 0; u < 4; u++) {
            int row = rows[u];
            int pos = atomicAdd(&g_roff[row], 1) + g_boff[row >> 10];
            g_ent[pos] = (unsigned)row | (b << 19);
        }
    }
    if (t < B) {
        int row = idx[t];
        int pos = atomicAdd(&g_roff[row], 1) + g_boff[row >> 10];
        g_ent[pos] = (unsigned)row | ((unsigned)t << 19) | (1u << 27);
    }
}

// --- fused: copy role (contiguous m range) || gather role (contiguous slabs)
//     bid-interleave keeps roles on ~the same row range -> L2 sharing;
//     row-sorted slabs -> L1 hits on repeated rows
__global__ void __launch_bounds__(256) k_fused(
        const float* __restrict__ mv1, const float* __restrict__ mv2,
        float* __restrict__ out) {
    int bid = blockIdx.x;
    int q = bid / 3;
    int r = bid - q * 3;
    int tid = threadIdx.x;
    int lane = tid & 31;
    int wrp  = tid >> 5;

    if (r == 2) {
        // ===== copy role: contiguous range of float4 positions, both banks
        const float4* b14 = (const float4*)mv1;
        const float4* b24 = (const float4*)mv2;
        float4* out4 = (float4*)out;
        long long mb = (long long)q * MPB;
        for (int mi = tid; mi < MPB; mi += 256) {
            long long m = mb + mi;
            if (m >= BANK4) break;
            float4 c1 = b14[m];
            float4 c2 = b24[m];
            float p1 = __shfl_up_sync(FULL, c1.w, 1);
            float p2 = __shfl_up_sync(FULL, c2.w, 1);
            if (lane == 0 && m > 0) {
                p1 = __ldg(&mv1[4 * m - 1]);
                p2 = __ldg(&mv2[4 * m - 1]);
            }
            if (m != 0) {
                __stcs(&out4[m],         make_float4(p1, c1.x, c1.y, c1.z));
                __stcs(&out4[BANK4 + m], make_float4(p2, c2.x, c2.y, c2.z));
            }
        }
        return;
    }

    // ===== gather role: contiguous slab of row-sorted entries, both views
    int g = q * 2 + r;                        // 0..GBLK-1
    int begin = g * EPB;
    int end = (g == GBLK - 1) ? ENT : begin + EPB;
    const float4* b14 = (const float4*)mv1;
    const float4* b24 = (const float4*)mv2;

    double acc0 = 0.0, acc1 = 0.0;

    for (int e0 = begin + wrp * 8; e0 < end; e0 += 64) {
        int cnt = min(8, end - e0);
        unsigned ent = 0;
        if (lane < cnt) ent = g_ent[e0 + lane];

        float4 w[8];
        float d0[8], d1[8];
        // batch 1: mv1 rows -> view1 (<mv1_row, f_t>)
        #pragma unroll
        for (int j = 0; j < 8; j++) {
            unsigned ej = __shfl_sync(FULL, ent, j);
            w[j] = b14[(long long)(ej & 0x7FFFFu) * 32 + lane];
        }
        #pragma unroll
        for (int j = 0; j < 8; j++) {
            unsigned ej = __shfl_sync(FULL, ent, j);
            uint2 ft = g_ftb[((ej >> 19) & 0xFFu) * 32 + lane];
            d1[j] = dotrf(w[j], ft);
        }
        // batch 2: mv2 rows -> view0 (<mv2_row, f_s>)
        #pragma unroll
        for (int j = 0; j < 8; j++) {
            unsigned ej = __shfl_sync(FULL, ent, j);
            w[j] = b24[(long long)(ej & 0x7FFFFu) * 32 + lane];
        }
        #pragma unroll
        for (int j = 0; j < 8; j++) {
            unsigned ej = __shfl_sync(FULL, ent, j);
            uint2 fs = g_fsb[((ej >> 19) & 0xFFu) * 32 + lane];
            d0[j] = dotrf(w[j], fs);
        }

        #pragma unroll
        for (int off = 16; off > 0; off >>= 1) {
            #pragma unroll
            for (int j = 0; j < 8; j++) {
                d0[j] += __shfl_xor_sync(FULL, d0[j], off);
                d1[j] += __shfl_xor_sync(FULL, d1[j], off);
            }
        }
        float my0 = d0[0], my1 = d1[0];
        #pragma unroll
        for (int j = 1; j < 8; j++)
            if (lane == j) { my0 = d0[j]; my1 = d1[j]; }

        if (lane < cnt) {
            float e0v = expf(my0 * kINV_T());
            float e1v = expf(my1 * kINV_T());
            bool pos = (ent >> 27) != 0;
            g_sc0[e0 + lane] = pos ? -e0v : e0v;
            g_sc1[e0 + lane] = pos ? -e1v : e1v;
            acc0 += (double)e0v;
            acc1 += (double)e1v;
        }
    }

    #pragma unroll
    for (int off = 16; off > 0; off >>= 1) {
        acc0 += __shfl_xor_sync(FULL, acc0, off);
        acc1 += __shfl_xor_sync(FULL, acc1, off);
    }
    __shared__ double shs[16];
    if (lane == 0) { shs[wrp] = acc0; shs[8 + wrp] = acc1; }
    __syncthreads();
    if (tid == 0) {
        double s0 = 0.0, s1 = 0.0;
        #pragma unroll
        for (int j = 0; j < 8; j++) { s0 += shs[j]; s1 += shs[8 + j]; }
        atomicAdd(&g_sum[0], s0);
        atomicAdd(&g_sum[1], s1);
    }
}

// --- loss reduction over sign-flagged score arrays
__global__ void __launch_bounds__(256) k2_loss() {
    double Z0 = g_sum[0] * (500000.0 / (double)ENT);
    double Z1 = g_sum[1] * (500000.0 / (double)ENT);
    float Zf0 = (float)Z0, Zf1 = (float)Z1;

    const int NT = 512 * 256;
    int tid = blockIdx.x * 256 + threadIdx.x;
    double acc = 0.0;

    #pragma unroll 4
    for (int i = tid; i < 2 * ENT; i += NT) {
        int v1 = (i >= ENT);
        float s = v1 ? g_sc1[i - ENT] : g_sc0[i];
        float Zf = v1 ? Zf1 : Zf0;
        float y = fabsf(s) / Zf;
        float t = (s < 0.0f) ? logf(y / (y + kDENOM()))
                             : logf(kMPN() / (y + kDENOM()));
        acc += (double)t;
    }

    #pragma unroll
    for (int off = 16; off > 0; off >>= 1)
        acc += __shfl_xor_sync(FULL, acc, off);
    __shared__ double sh[8];
    int lane = threadIdx.x & 31, wid = threadIdx.x >> 5;
    if (lane == 0) sh[wid] = acc;
    __syncthreads();
    if (threadIdx.x == 0) {
        double s = 0.0;
        for (int j = 0; j < 8; j++) s += sh[j];
        atomicAdd(&g_loss, s);
    }
}

// --- momentum scatter update of the 256 touched rows
__global__ void k3_update(const float* __restrict__ f_s, const float* __restrict__ f_t,
                          const float* __restrict__ mv1, const float* __restrict__ mv2,
                          const int* __restrict__ idx, float* __restrict__ out) {
    int u = blockIdx.x;       // 512 blocks
    int v = u >> 8;
    int b = u & 255;
    if (!g_winner[b]) return;
    int row = idx[b];
    const float* mem = v ? mv2 : mv1;
    const float* f   = v ? f_t : f_s;
    float* dst = out + 1 + (size_t)v * BANK + (size_t)row * D;
    int t = threadIdx.x;      // 128 threads
    float nv = mem[(long long)row * D + t] * 0.5f + f[b * D + t] * 0.5f;
    float s = nv * nv;
    #pragma unroll
    for (int off = 16; off > 0; off >>= 1)
        s += __shfl_xor_sync(FULL, s, off);
    __shared__ float sh[4];
    if ((t & 31) == 0) sh[t >> 5] = s;
    __syncthreads();
    float tot = sh[0] + sh[1] + sh[2] + sh[3];
    dst[t] = nv / sqrtf(tot);
}

__global__ void k_final(float* __restrict__ out) {
    out[0] = (float)(-g_loss / 256.0);
}

extern "C" void kernel_launch(void* const* d_in, const int* in_sizes, int n_in,
                              void* d_out, int out_size) {
    const float* f_s  = (const float*)d_in[0];
    const float* f_t  = (const float*)d_in[1];
    const float* mv1  = (const float*)d_in[2];
    const float* mv2  = (const float*)d_in[3];
    const int*   idx  = (const int*)d_in[4];
    const int*   cidx = (const int*)d_in[5];
    float* out = (float*)d_out;

    k_zero<<<512, 256>>>(idx, f_s, f_t, mv1, mv2, out);
    k_hist<<<512, 256>>>(idx, cidx);
    k_scanA<<<SCAN_BLK, 1024>>>();
    k_scanB<<<1, 512>>>();
    k_scatter<<<512, 256>>>(idx, cidx);
    k_fused<<<TBLK, 256>>>(mv1, mv2, out);
    k2_loss<<<512, 256>>>();
    k3_update<<<512, 128>>>(f_s, f_t, mv1, mv2, idx, out);
    k_final<<<1, 1>>>(out);
}